// round 17
// baseline (speedup 1.0000x reference)
#include <cuda_runtime.h>
#include <cuda_fp16.h>
#include <math.h>
#include <stdint.h>

// ---------------------------------------------------------------------------
// Problem constants
// ---------------------------------------------------------------------------
#define Bb   32
#define Cc   128
#define Pp   128
#define Nn   (Bb * Pp)    // 4096 rows
#define Kk   510
#define KL   512
#define Zz   128
#define DS   256
#define HW   4096
#define EPSV 1e-5f
#define INV_NORM 0.08838834764831845f

#define KP   512
#define Ntot 16384        // 4*HW

// output layout
#define OFF_W   0
#define OFF_L   (Nn * KL)
#define OFF_LP  (2 * Nn * KL)
#define OFF_S   (3 * Nn * KL)

// GEMM tiling: CTA 128Mx64N x TK32, 4 warps, 3-stage pipeline, 4 CTAs/SM
#define TM 128
#define TN 64
#define TK 32                  // fp16 per k-chunk (64 B per row)
#define NCHUNK (KP / TK)       // 16
#define RP 80                  // smem row pitch (64B data + 16B pad)
#define A_TILE_BYTES (TM * RP) // 10240
#define B_TILE_BYTES (TN * RP) // 5120
#define STAGE_BYTES (A_TILE_BYTES + B_TILE_BYTES)  // 15360
#define STAGES 3
#define SMEM_DYN (STAGES * STAGE_BYTES)   // 46080

// fused launch-1 block ranges: lat -> prep -> row
#define NB_LAT  128
#define NB_PREP 2048
#define NB_ROW  512
#define BID_PREP (NB_LAT)
#define BID_ROW  (NB_LAT + NB_PREP)

// ---------------------------------------------------------------------------
// Device scratch (zero-initialized; rows k>=510 of g_spT stay zero)
// ---------------------------------------------------------------------------
__device__ __align__(16) float  g_lat[Kk * Zz];
__device__ __align__(16) __half g_wA [Nn * KP];            // 4.2 MB
__device__ __align__(16) __half g_spT[(size_t)Ntot * KP];  // 16.8 MB
__device__ int g_sync = 0;                                  // lat-done counter

// ---------------------------------------------------------------------------
// PTX helpers (sm_80-era; valid on plain compute_103 target)
// ---------------------------------------------------------------------------
__device__ __forceinline__ uint32_t smem_u32(const void* p) {
    uint32_t a;
    asm("{ .reg .u64 t; cvta.to.shared.u64 t, %1; cvt.u32.u64 %0, t; }"
        : "=r"(a) : "l"(p));
    return a;
}
#define CP_ASYNC16(dst, src) \
    asm volatile("cp.async.cg.shared.global [%0], [%1], 16;" :: "r"(dst), "l"(src))
#define CP_COMMIT() asm volatile("cp.async.commit_group;" ::: "memory")
#define CP_WAIT1()  asm volatile("cp.async.wait_group 1;" ::: "memory")

#define LDSM4(r0, r1, r2, r3, addr) \
    asm volatile("ldmatrix.sync.aligned.m8n8.x4.shared.b16 {%0,%1,%2,%3}, [%4];" \
        : "=r"(r0), "=r"(r1), "=r"(r2), "=r"(r3) : "r"(addr))

__device__ __forceinline__ void mma16816(float* c, const uint32_t* a,
                                         const uint32_t* b) {
    asm volatile(
        "mma.sync.aligned.m16n8k16.row.col.f32.f16.f16.f32 "
        "{%0,%1,%2,%3}, {%4,%5,%6,%7}, {%8,%9}, {%0,%1,%2,%3};"
        : "+f"(c[0]), "+f"(c[1]), "+f"(c[2]), "+f"(c[3])
        : "r"(a[0]), "r"(a[1]), "r"(a[2]), "r"(a[3]), "r"(b[0]), "r"(b[1]));
}

// ---------------------------------------------------------------------------
// R-row block reductions over 128 threads
// ---------------------------------------------------------------------------
template <int R>
__device__ __forceinline__ void redsumN(float v[R], float red[4][R], int t) {
    #pragma unroll
    for (int o = 16; o; o >>= 1)
        #pragma unroll
        for (int r = 0; r < R; r++) v[r] += __shfl_down_sync(0xffffffffu, v[r], o);
    if ((t & 31) == 0)
        #pragma unroll
        for (int r = 0; r < R; r++) red[t >> 5][r] = v[r];
    __syncthreads();
    #pragma unroll
    for (int r = 0; r < R; r++)
        v[r] = red[0][r] + red[1][r] + red[2][r] + red[3][r];
    __syncthreads();
}
template <int R>
__device__ __forceinline__ void redmaxN(float v[R], float red[4][R], int t) {
    #pragma unroll
    for (int o = 16; o; o >>= 1)
        #pragma unroll
        for (int r = 0; r < R; r++)
            v[r] = fmaxf(v[r], __shfl_down_sync(0xffffffffu, v[r], o));
    if ((t & 31) == 0)
        #pragma unroll
        for (int r = 0; r < R; r++) red[t >> 5][r] = v[r];
    __syncthreads();
    #pragma unroll
    for (int r = 0; r < R; r++)
        v[r] = fmaxf(fmaxf(red[0][r], red[1][r]), fmaxf(red[2][r], red[3][r]));
    __syncthreads();
}

// ---------------------------------------------------------------------------
// Shared-memory overlays for the fused kernel (lat | prep | row)
// ---------------------------------------------------------------------------
struct LatSh {
    float lv[4][DS];
    float lws[128][33];
    float red[4][4];
};
struct RowSh {
    float xv[8][Cc];
    float av[8][Zz];
    float lg[8][KL];
    float red[4][8];
};
struct PrepSh { float tile[64][65]; };

#define MAXSH(a, b) ((a) > (b) ? (a) : (b))
#define SHBYTES MAXSH(sizeof(LatSh), MAXSH(sizeof(RowSh), sizeof(PrepSh)))

// ---------------------------------------------------------------------------
// Fused launch 1 (identical to round-16 best):
//   bids [0, 128)        -> k_lat
//   bids [128, 2176)     -> k_prep
//   bids [2176, 2688)    -> k_row
// ---------------------------------------------------------------------------
__global__ void __launch_bounds__(128) k_fused(
        const float* __restrict__ latents,
        const float* __restrict__ lw,
        const float* __restrict__ lb,
        const float* __restrict__ x,
        const float* __restrict__ blankl,
        const float* __restrict__ aw,
        const float* __restrict__ ab,
        const float* __restrict__ proto,
        const float* __restrict__ masks,
        float* __restrict__ out) {
    __shared__ __align__(16) char shbuf[SHBYTES];
    int t = threadIdx.x;
    int bid = blockIdx.x;

    if (bid < NB_LAT) {
        // ================= k_lat: 4 latents per block ======================
        LatSh& sh = *(LatSh*)shbuf;
        int k0 = bid * 4;

        #pragma unroll
        for (int r = 0; r < 4; r++) {
            int k = k0 + r;
            float a = 0.f, b2 = 0.f;
            if (k < Kk) { a = latents[k * DS + t]; b2 = latents[k * DS + t + 128]; }
            sh.lv[r][t] = a; sh.lv[r][t + 128] = b2;
        }
        __syncthreads();

        float s[4] = {lb[t], lb[t], lb[t], lb[t]};
        for (int dt = 0; dt < 8; dt++) {
            int d0 = dt * 32;
            #pragma unroll
            for (int i = 0; i < 32; i++) {
                int idx = i * 128 + t;
                int z = idx >> 5, dd = idx & 31;
                sh.lws[z][dd] = lw[z * DS + d0 + dd];
            }
            __syncthreads();
            #pragma unroll 8
            for (int dd = 0; dd < 32; dd++) {
                float w = sh.lws[t][dd];
                #pragma unroll
                for (int r = 0; r < 4; r++) s[r] += sh.lv[r][d0 + dd] * w;
            }
            __syncthreads();
        }

        float v[4];
        #pragma unroll
        for (int r = 0; r < 4; r++) v[r] = s[r];
        redsumN<4>(v, sh.red, t);
        float d4[4];
        #pragma unroll
        for (int r = 0; r < 4; r++) {
            d4[r] = s[r] - v[r] * (1.f / 128.f);
            v[r] = d4[r] * d4[r];
        }
        redsumN<4>(v, sh.red, t);
        #pragma unroll
        for (int r = 0; r < 4; r++) {
            int k = k0 + r;
            if (k < Kk)
                g_lat[k * Zz + t] = d4[r] * rsqrtf(v[r] * (1.f / 128.f) + EPSV);
        }
        __threadfence();
        __syncthreads();
        if (t == 0) atomicAdd(&g_sync, 1);
        return;
    }

    if (bid < BID_ROW) {
        // ================= k_prep: sprite^T fp16 (vectorized) ==============
        PrepSh& sh = *(PrepSh*)shbuf;
        int bi = bid - BID_PREP;           // 0..2047
        int n0 = (bi & 255) * 64;
        int k0 = (bi >> 8) * 64;

        for (int idx = t; idx < 1024; idx += 128) {
            int kk = idx >> 4;
            int nn = (idx & 15) * 4;
            int k = k0 + kk, n = n0 + nn;
            int ch = n >> 12, i = n & 4095;
            float4 s = make_float4(0.f, 0.f, 0.f, 0.f);
            if (k < Kk) {
                const float* src = (ch < 3)
                    ? proto + (size_t)k * (3 * HW) + ch * HW + i
                    : masks + (size_t)k * HW + i;
                s = *(const float4*)src;
            }
            sh.tile[kk][nn]     = s.x;
            sh.tile[kk][nn + 1] = s.y;
            sh.tile[kk][nn + 2] = s.z;
            sh.tile[kk][nn + 3] = s.w;
        }
        __syncthreads();

        for (int idx = t; idx < 1024; idx += 128) {
            int nn = idx >> 4;
            int kk = (idx & 15) * 4;
            if (k0 + kk < Kk) {
                __half2 h01 = __floats2half2_rn(sh.tile[kk][nn],
                                                sh.tile[kk + 1][nn]);
                float f2 = (k0 + kk + 2 < Kk) ? sh.tile[kk + 2][nn] : 0.f;
                float f3 = (k0 + kk + 3 < Kk) ? sh.tile[kk + 3][nn] : 0.f;
                __half2 h23 = __floats2half2_rn(f2, f3);
                __half2* dst = (__half2*)(g_spT + (size_t)(n0 + nn) * KP
                                          + k0 + kk);
                dst[0] = h01;
                dst[1] = h23;
            }
        }
        return;
    }

    // ================= k_row: 8 rows per block =============================
    RowSh& sh = *(RowSh*)shbuf;
    int bi = bid - BID_ROW;       // 0..511
    int p  = bi & 127;
    int bq = bi >> 7;

    #pragma unroll
    for (int r = 0; r < 8; r++)
        sh.xv[r][t] = x[(size_t)(bq * 8 + r) * (Cc * Pp) + t * Pp + p];

    if (t == 0) {
        while (atomicAdd(&g_sync, 0) < NB_LAT) __nanosleep(128);
    }
    __syncthreads();
    __threadfence();

    // anchors linear + LN (8 rows) — float4 smem reads
    {
        const float4* wrow4 = (const float4*)(aw + t * Cc);
        float s[8];
        #pragma unroll
        for (int r = 0; r < 8; r++) s[r] = ab[t];
        #pragma unroll 4
        for (int c4 = 0; c4 < Cc / 4; c4++) {
            float4 w = wrow4[c4];
            #pragma unroll
            for (int r = 0; r < 8; r++) {
                float4 xr = *(const float4*)&sh.xv[r][c4 * 4];
                s[r] += xr.x * w.x + xr.y * w.y + xr.z * w.z + xr.w * w.w;
            }
        }
        float v[8];
        #pragma unroll
        for (int r = 0; r < 8; r++) v[r] = s[r];
        redsumN<8>(v, sh.red, t);
        float d8[8];
        #pragma unroll
        for (int r = 0; r < 8; r++) {
            d8[r] = s[r] - v[r] * (1.f / 128.f);
            v[r] = d8[r] * d8[r];
        }
        redsumN<8>(v, sh.red, t);
        #pragma unroll
        for (int r = 0; r < 8; r++)
            sh.av[r][t] = d8[r] * rsqrtf(v[r] * (1.f / 128.f) + EPSV);
    }

    // blank dots (8 rows)
    float lgb[8];
    {
        float bl = blankl[(p & 1) * Cc + t];
        float v[8];
        #pragma unroll
        for (int r = 0; r < 8; r++) v[r] = sh.xv[r][t] * bl;
        redsumN<8>(v, sh.red, t);
        #pragma unroll
        for (int r = 0; r < 8; r++) lgb[r] = v[r] * INV_NORM;
    }
    __syncthreads();

    // logits (float4 LDS)
    #pragma unroll
    for (int j = 0; j < 4; j++) {
        int k = t + (j << 7);
        if (k < Kk) {
            const float4* lr = (const float4*)(g_lat + k * Zz);
            float acc[8] = {0.f, 0.f, 0.f, 0.f, 0.f, 0.f, 0.f, 0.f};
            #pragma unroll 4
            for (int i = 0; i < 32; i++) {
                float4 q = lr[i];
                #pragma unroll
                for (int r = 0; r < 8; r++) {
                    float4 a4 = *(const float4*)&sh.av[r][4 * i];
                    acc[r] += q.x * a4.x + q.y * a4.y + q.z * a4.z + q.w * a4.w;
                }
            }
            #pragma unroll
            for (int r = 0; r < 8; r++) sh.lg[r][k] = acc[r] * INV_NORM;
        } else {
            #pragma unroll
            for (int r = 0; r < 8; r++) sh.lg[r][k] = lgb[r];
        }
    }
    __syncthreads();

    // softmax over 512, 8 rows
    float v[8];
    #pragma unroll
    for (int r = 0; r < 8; r++) {
        float m = -1e30f;
        #pragma unroll
        for (int j = 0; j < 4; j++) m = fmaxf(m, sh.lg[r][t + (j << 7)]);
        v[r] = m;
    }
    redmaxN<8>(v, sh.red, t);
    float mx[8];
    #pragma unroll
    for (int r = 0; r < 8; r++) mx[r] = v[r];

    float ev[8][4];
    #pragma unroll
    for (int r = 0; r < 8; r++) {
        float s = 0.f;
        #pragma unroll
        for (int j = 0; j < 4; j++) {
            ev[r][j] = expf(sh.lg[r][t + (j << 7)] - mx[r]);
            s += ev[r][j];
        }
        v[r] = s;
    }
    redsumN<8>(v, sh.red, t);

    #pragma unroll
    for (int r = 0; r < 8; r++) {
        int b = bq * 8 + r;
        int n = (b << 7) + p;
        int m = (p << 5) + b;
        float inv_sum = 1.0f / v[r];
        float lse = mx[r] + logf(v[r]);
        float* out_w  = out + OFF_W  + (size_t)n * KL;
        float* out_l  = out + OFF_L  + (size_t)n * KL;
        float* out_lp = out + OFF_LP + (size_t)m * KL;
        __half* wa = g_wA + (size_t)m * KP;
        #pragma unroll
        for (int j = 0; j < 4; j++) {
            int k = t + (j << 7);
            float l = sh.lg[r][k];
            float w = ev[r][j] * inv_sum;
            out_w[k]  = w;
            out_l[k]  = l;
            out_lp[k] = l - lse;
            wa[k] = __float2half(w);
        }
    }
}

// ---------------------------------------------------------------------------
// Kernel 4: mma.sync fp16 GEMM  C[4096,16384] = A[4096,512] @ B[16384,512]^T
// CTA 128Mx64N, 4 warps (warp tile 32x64), TK=32, 3-stage pipeline, 4 CTAs/SM
// ---------------------------------------------------------------------------
__global__ void __launch_bounds__(128, 4) k_gemm(float* __restrict__ outS) {
    extern __shared__ __align__(128) char sm[];   // STAGES x [A|B]

    // reset the fused-kernel sync counter for the next graph replay
    if (blockIdx.x == 0 && blockIdx.y == 0 && threadIdx.x == 0) g_sync = 0;

    int t = threadIdx.x;
    int lane = t & 31;
    int warp_m = t >> 5;           // 0..3 -> 32-row slice; warp covers all 64 N
    int n0 = blockIdx.x * TN;
    int m0 = blockIdx.y * TM;

    uint32_t smb = smem_u32(sm);

    // cp.async mapping: per chunk, A = 512 16B-units (4/thread),
    // B = 256 16B-units (2/thread). row = t>>2 (+32j), col = (t&3)*16.
    int qr = t >> 2, qc = t & 3;

    const char* gA = (const char*)g_wA  + (size_t)(m0 + qr) * (KP * 2) + qc * 16;
    const char* gB = (const char*)g_spT + (size_t)(n0 + qr) * (KP * 2) + qc * 16;
    const size_t gstep = (size_t)32 * (KP * 2);   // +32 rows

    uint32_t sA = smb + qr * RP + qc * 16;
    uint32_t sB = smb + A_TILE_BYTES + qr * RP + qc * 16;
    const uint32_t sstep = 32 * RP;

    uint32_t lmA = smb + (warp_m * 32 + (lane & 15)) * RP + (lane >> 4) * 16;
    uint32_t lmB = smb + A_TILE_BYTES
                 + ((lane & 7) + ((lane >> 4) & 1) * 8) * RP
                 + ((lane >> 3) & 1) * 16;

    float acc[2][8][4];
    #pragma unroll
    for (int mt = 0; mt < 2; mt++)
        #pragma unroll
        for (int nt = 0; nt < 8; nt++)
            #pragma unroll
            for (int q = 0; q < 4; q++) acc[mt][nt][q] = 0.f;

    // prefetch chunks 0,1 into stages 0,1
    #pragma unroll
    for (int s = 0; s < STAGES - 1; s++) {
        uint32_t so = s * STAGE_BYTES;
        int cb = s * 64;
        #pragma unroll
        for (int j = 0; j < 4; j++)
            CP_ASYNC16(sA + so + j * sstep, gA + cb + j * gstep);
        #pragma unroll
        for (int j = 0; j < 2; j++)
            CP_ASYNC16(sB + so + j * sstep, gB + cb + j * gstep);
        CP_COMMIT();
    }

    for (int c = 0; c < NCHUNK; c++) {
        CP_WAIT1();            // chunk c landed
        __syncthreads();       // 4 warps past compute of c-1 -> stage reuse safe

        int cn = c + STAGES - 1;
        if (cn < NCHUNK) {
            uint32_t so = (cn % STAGES) * STAGE_BYTES;
            int cb = cn * 64;
            #pragma unroll
            for (int j = 0; j < 4; j++)
                CP_ASYNC16(sA + so + j * sstep, gA + cb + j * gstep);
            #pragma unroll
            for (int j = 0; j < 2; j++)
                CP_ASYNC16(sB + so + j * sstep, gB + cb + j * gstep);
        }
        CP_COMMIT();

        uint32_t aoff = lmA + (c % STAGES) * STAGE_BYTES;
        uint32_t boff = lmB + (c % STAGES) * STAGE_BYTES;
        #pragma unroll
        for (int kt = 0; kt < 2; kt++) {
            uint32_t a[2][4];
            #pragma unroll
            for (int mt = 0; mt < 2; mt++)
                LDSM4(a[mt][0], a[mt][1], a[mt][2], a[mt][3],
                      aoff + mt * (16 * RP) + kt * 32);
            uint32_t bfr[8][2];
            #pragma unroll
            for (int pg = 0; pg < 4; pg++)
                LDSM4(bfr[2 * pg][0], bfr[2 * pg][1],
                      bfr[2 * pg + 1][0], bfr[2 * pg + 1][1],
                      boff + pg * (16 * RP) + kt * 32);
            #pragma unroll
            for (int mt = 0; mt < 2; mt++)
                #pragma unroll
                for (int nt = 0; nt < 8; nt++)
                    mma16816(acc[mt][nt], a[mt], bfr[nt]);
        }
    }

    // epilogue
    int rbase = m0 + warp_m * 32 + (lane >> 2);
    int cbase = n0 + (lane & 3) * 2;
    #pragma unroll
    for (int mt = 0; mt < 2; mt++) {
        #pragma unroll
        for (int nt = 0; nt < 8; nt++) {
            int r = rbase + mt * 16;
            int cc = cbase + nt * 8;
            *(float2*)(outS + (size_t)r * Ntot + cc) =
                make_float2(acc[mt][nt][0], acc[mt][nt][1]);
            *(float2*)(outS + (size_t)(r + 8) * Ntot + cc) =
                make_float2(acc[mt][nt][2], acc[mt][nt][3]);
        }
    }
}

// ---------------------------------------------------------------------------
// Launch
// ---------------------------------------------------------------------------
extern "C" void kernel_launch(void* const* d_in, const int* in_sizes, int n_in,
                              void* d_out, int out_size) {
    const float* x       = (const float*)d_in[0];
    const float* latents = (const float*)d_in[1];
    const float* blankl  = (const float*)d_in[2];
    const float* lw      = (const float*)d_in[3];
    const float* lb      = (const float*)d_in[4];
    const float* aw      = (const float*)d_in[5];
    const float* ab      = (const float*)d_in[6];
    const float* proto   = (const float*)d_in[7];
    const float* masks   = (const float*)d_in[8];
    float* out = (float*)d_out;

    static int smem_set = 0;
    if (!smem_set) {
        cudaFuncSetAttribute(k_gemm, cudaFuncAttributeMaxDynamicSharedMemorySize,
                             SMEM_DYN);
        smem_set = 1;
    }

    // launch 1: lat (0..127) + prep (128..2175) + row (2176..2687)
    k_fused<<<NB_LAT + NB_PREP + NB_ROW, 128>>>(
        latents, lw, lb, x, blankl, aw, ab, proto, masks, out);
    // launch 2: tensor-core GEMM (needs g_wA, g_spT); also resets g_sync
    dim3 gg(Ntot / TN, Nn / TM);
    k_gemm<<<gg, 128, SMEM_DYN>>>(out + OFF_S);
}